// round 16
// baseline (speedup 1.0000x reference)
#include <cuda_runtime.h>
#include <cuda_fp16.h>
#include <cuda_bf16.h>
#include <stdint.h>
#include <math.h>

// Problem constants
#define NROWS 512          // 256 pairs * 2 spectra
#define NPEAK 512          // peaks per spectrum
#define GROUPS 3333
#define BOUT 9999          // 3333 * 3
#define BOUTP 10016        // padded K for GEMM0 (mult of 32)
#define H0 1000
#define H0P 1024           // padded K for GEMM1
#define H1 800
#define H2 800
#define HE 400

// -------------------- scratch (device globals; zero-initialized) --------------------
__device__ float4 g_entries[NROWS * NPEAK];                // compacted per row
__device__ int    g_cnt[NROWS];
__device__ __half g_xs[NROWS * BOUTP];                     // dense layer-0 input, 10.3 MB
__device__ __half g_w0h[BOUTP * H0];                       // fp16 w0, pad rows zero-init
__device__ __half g_w1h[H0P * H1];                         // pad rows 1000..1023 zero-init
__device__ __half g_w2h[H1 * H2];
__device__ __half g_weh[H2 * HE];
__device__ __half g_h0h[NROWS * H0P];                      // pad cols zero-init
__device__ __half g_h1h[NROWS * H1];
__device__ __half g_h2h[NROWS * H2];
__device__ float  g_emb[NROWS * HE];

// ---- K1: build per-peak entries, compacted (order-preserving prefix scan) ----
__global__ void __launch_bounds__(512) k_build(
    const float* __restrict__ mz, const float* __restrict__ inten,
    const float* __restrict__ binner_w)
{
    __shared__ int s_wcnt[16];
    __shared__ int s_wbase[16];
    int row = blockIdx.x;
    int p   = threadIdx.x;
    int idx = row * NPEAK + p;
    float m  = mz[idx];
    float it = inten[idx];
    float fb = __fdiv_rn(m, 0.01f);
    int b = (int)fb;
    bool valid = (m >= 0.0f && m < 1000.0f && b >= 0 && b < GROUPS * 30);

    float4 e = make_float4(0.f, 0.f, 0.f, 0.f);
    if (valid) {
        int g = b / 30;
        int i = b - g * 30;
        float v = sqrtf(it);              // inten ** 0.5
        const float* bw = binner_w + (g * 30 + i) * 3;
        e = make_float4(v * bw[0], v * bw[1], v * bw[2], __int_as_float(3 * g));
    }

    unsigned int mask = __ballot_sync(0xffffffffu, valid);
    int lane = p & 31, w = p >> 5;
    int pos_in_warp = __popc(mask & ((1u << lane) - 1u));
    if (lane == 0) s_wcnt[w] = __popc(mask);
    __syncthreads();
    if (p == 0) {
        int run = 0;
        #pragma unroll
        for (int i = 0; i < 16; i++) { s_wbase[i] = run; run += s_wcnt[i]; }
        g_cnt[row] = run;
    }
    __syncthreads();
    if (valid)
        g_entries[row * NPEAK + s_wbase[w] + pos_in_warp] = e;
}

// ---- K2: weight fp32 -> fp16 streaming converter ----
__global__ void __launch_bounds__(256) k_wconv(
    const float* __restrict__ src, __half* __restrict__ dst, int nsrc4)
{
    int f = blockIdx.x * blockDim.x + threadIdx.x;
    if (f >= nsrc4) return;
    float4 v = ((const float4*)src)[f];
    __half2 lo = __floats2half2_rn(v.x, v.y);
    __half2 hi = __floats2half2_rn(v.z, v.w);
    uint2 o;
    o.x = *(const unsigned int*)&lo;
    o.y = *(const unsigned int*)&hi;
    ((uint2*)dst)[f] = o;
}

// ---- K3: build dense xs row: xs = binner_b_flat + scatter(entries), fp16 out ----
// One block per row. Deterministic: serial scatter in fixed entry order, one
// lane per column-offset (0/1/2), so same-column collisions resolve in order.
__global__ void __launch_bounds__(128) k_xs(const float* __restrict__ bbf)
{
    __shared__ float xsrow[BOUTP];       // 40064 B
    __shared__ float4 se[NPEAK];         // 8192 B
    int row = blockIdx.x;
    int t = threadIdx.x;
    int cnt = g_cnt[row];

    for (int i = t; i < BOUTP; i += 128)
        xsrow[i] = (i < BOUT) ? bbf[i] : 0.f;
    for (int i = t; i < NPEAK; i += 128)
        se[i] = g_entries[row * NPEAK + i];
    __syncthreads();

    if (t < 3) {
        for (int e = 0; e < cnt; e++) {
            float4 E = se[e];
            int cb = __float_as_int(E.w);
            float v = (t == 0) ? E.x : ((t == 1) ? E.y : E.z);
            xsrow[cb + t] += v;
        }
    }
    __syncthreads();

    // fp32 smem -> fp16 gmem, coalesced
    uint2* dst = (uint2*)(g_xs + (size_t)row * BOUTP);
    for (int i4 = t; i4 < BOUTP / 4; i4 += 128) {
        float4 v = *(const float4*)&xsrow[i4 * 4];
        __half2 lo = __floats2half2_rn(v.x, v.y);
        __half2 hi = __floats2half2_rn(v.z, v.w);
        uint2 o;
        o.x = *(const unsigned int*)&lo;
        o.y = *(const unsigned int*)&hi;
        dst[i4] = o;
    }
}

// -------------------- K4: fp16 tensor-core GEMM (register-prefetch pipelined) ----
// C = act(A @ W + bias). A:[M,Kp] fp16 row-major (Kp%32==0, zero-padded),
// W:[Kp,N] fp16 row-major. BM=BN=64, BK=32, 128 threads (4 warps, 2x2),
// warp tile 32x32 via mma.m16n8k16 (2 m-tiles x 4 n-tiles).
#define GA_STRIDE 40   // halves; 80B rows -> conflict-free ldmatrix (gcd(5,8)=1)
#define GB_STRIDE 72   // halves; 144B rows (gcd(9,8)=1)

__device__ __forceinline__ void ldsm_x4(unsigned int addr,
    unsigned int &r0, unsigned int &r1, unsigned int &r2, unsigned int &r3)
{
    asm volatile("ldmatrix.sync.aligned.m8n8.x4.shared.b16 {%0,%1,%2,%3}, [%4];"
        : "=r"(r0), "=r"(r1), "=r"(r2), "=r"(r3) : "r"(addr));
}
__device__ __forceinline__ void ldsm_x4t(unsigned int addr,
    unsigned int &r0, unsigned int &r1, unsigned int &r2, unsigned int &r3)
{
    asm volatile("ldmatrix.sync.aligned.m8n8.x4.trans.shared.b16 {%0,%1,%2,%3}, [%4];"
        : "=r"(r0), "=r"(r1), "=r"(r2), "=r"(r3) : "r"(addr));
}
__device__ __forceinline__ void mma16816(float* c,
    unsigned int a0, unsigned int a1, unsigned int a2, unsigned int a3,
    unsigned int b0, unsigned int b1)
{
    asm volatile("mma.sync.aligned.m16n8k16.row.col.f32.f16.f16.f32 "
        "{%0,%1,%2,%3}, {%4,%5,%6,%7}, {%8,%9}, {%0,%1,%2,%3};"
        : "+f"(c[0]), "+f"(c[1]), "+f"(c[2]), "+f"(c[3])
        : "r"(a0), "r"(a1), "r"(a2), "r"(a3), "r"(b0), "r"(b1));
}

__global__ void __launch_bounds__(128) k_hgemm(
    const __half* __restrict__ A, const __half* __restrict__ W,
    const float* __restrict__ bias, __half* __restrict__ Ch,
    float* __restrict__ Cf, int Kp, int N, int Nout, int relu)
{
    __shared__ __half sA[64 * GA_STRIDE];
    __shared__ __half sB[32 * GB_STRIDE];

    int t = threadIdx.x;
    int m0 = blockIdx.y * 64;
    int n0 = blockIdx.x * 64;
    int lane = t & 31, warp = t >> 5;
    int m_base = (warp >> 1) * 32;
    int n_base = (warp & 1) * 32;

    int ai0 = 2 * t, ai1 = 2 * t + 1;
    int ar0 = ai0 >> 2, ac0 = (ai0 & 3) * 8;
    int ar1 = ai1 >> 2, ac1 = (ai1 & 3) * 8;
    int br0 = ai0 >> 3, bc0 = (ai0 & 7) * 8;
    int br1 = ai1 >> 3, bc1 = (ai1 & 7) * 8;
    bool bp0 = (n0 + bc0) < N;
    bool bp1 = (n0 + bc1) < N;

    int mat = lane >> 3, r = lane & 7;
    unsigned int sA_u = (unsigned int)__cvta_generic_to_shared(sA);
    unsigned int sB_u = (unsigned int)__cvta_generic_to_shared(sB);
    unsigned int aaddr[2][2];
    unsigned int baddr[2][2];
    #pragma unroll
    for (int mt = 0; mt < 2; mt++)
        #pragma unroll
        for (int ks = 0; ks < 2; ks++)
            aaddr[mt][ks] = sA_u + (unsigned int)(((m_base + mt * 16 + (mat & 1) * 8 + r)
                            * GA_STRIDE + ks * 16 + (mat >> 1) * 8) * 2);
    #pragma unroll
    for (int pr = 0; pr < 2; pr++)
        #pragma unroll
        for (int ks = 0; ks < 2; ks++)
            baddr[pr][ks] = sB_u + (unsigned int)(((ks * 16 + (mat & 1) * 8 + r)
                            * GB_STRIDE + n_base + pr * 16 + (mat >> 1) * 8) * 2);

    float acc[2][4][4];
    #pragma unroll
    for (int mt = 0; mt < 2; mt++)
        #pragma unroll
        for (int nt = 0; nt < 4; nt++)
            #pragma unroll
            for (int i = 0; i < 4; i++) acc[mt][nt][i] = 0.f;

    const uint4 zero4 = make_uint4(0u, 0u, 0u, 0u);
    int KT = Kp >> 5;

    // prologue: load tile 0 into registers
    uint4 av0 = *(const uint4*)(A + (size_t)(m0 + ar0) * Kp + ac0);
    uint4 av1 = *(const uint4*)(A + (size_t)(m0 + ar1) * Kp + ac1);
    uint4 bv0 = bp0 ? *(const uint4*)(W + (size_t)br0 * N + n0 + bc0) : zero4;
    uint4 bv1 = bp1 ? *(const uint4*)(W + (size_t)br1 * N + n0 + bc1) : zero4;

    for (int kt = 0; kt < KT; kt++) {
        __syncthreads();   // previous compute done reading smem
        *(uint4*)(sA + ar0 * GA_STRIDE + ac0) = av0;
        *(uint4*)(sA + ar1 * GA_STRIDE + ac1) = av1;
        *(uint4*)(sB + br0 * GB_STRIDE + bc0) = bv0;
        *(uint4*)(sB + br1 * GB_STRIDE + bc1) = bv1;
        __syncthreads();

        // issue next tile's loads; latency hides behind the MMA section below
        if (kt + 1 < KT) {
            int k0 = (kt + 1) * 32;
            av0 = *(const uint4*)(A + (size_t)(m0 + ar0) * Kp + k0 + ac0);
            av1 = *(const uint4*)(A + (size_t)(m0 + ar1) * Kp + k0 + ac1);
            bv0 = bp0 ? *(const uint4*)(W + (size_t)(k0 + br0) * N + n0 + bc0) : zero4;
            bv1 = bp1 ? *(const uint4*)(W + (size_t)(k0 + br1) * N + n0 + bc1) : zero4;
        }

        #pragma unroll
        for (int ks = 0; ks < 2; ks++) {
            unsigned int af[2][4];
            ldsm_x4(aaddr[0][ks], af[0][0], af[0][1], af[0][2], af[0][3]);
            ldsm_x4(aaddr[1][ks], af[1][0], af[1][1], af[1][2], af[1][3]);
            unsigned int bf[4][2];
            ldsm_x4t(baddr[0][ks], bf[0][0], bf[0][1], bf[1][0], bf[1][1]);
            ldsm_x4t(baddr[1][ks], bf[2][0], bf[2][1], bf[3][0], bf[3][1]);
            #pragma unroll
            for (int mt = 0; mt < 2; mt++)
                #pragma unroll
                for (int nt = 0; nt < 4; nt++)
                    mma16816(acc[mt][nt], af[mt][0], af[mt][1], af[mt][2], af[mt][3],
                             bf[nt][0], bf[nt][1]);
        }
    }

    int gid = lane >> 2, tig = lane & 3;
    #pragma unroll
    for (int mt = 0; mt < 2; mt++) {
        int row0 = m0 + m_base + mt * 16 + gid;
        #pragma unroll
        for (int nt = 0; nt < 4; nt++) {
            int col = n0 + n_base + nt * 8 + tig * 2;
            if (col < N) {
                float bb0 = bias[col], bb1 = bias[col + 1];
                float v0 = acc[mt][nt][0] + bb0;
                float v1 = acc[mt][nt][1] + bb1;
                float v2 = acc[mt][nt][2] + bb0;
                float v3 = acc[mt][nt][3] + bb1;
                if (relu) {
                    v0 = fmaxf(v0, 0.f); v1 = fmaxf(v1, 0.f);
                    v2 = fmaxf(v2, 0.f); v3 = fmaxf(v3, 0.f);
                }
                if (Cf) {
                    *(float2*)(Cf + (size_t)row0 * Nout + col)       = make_float2(v0, v1);
                    *(float2*)(Cf + (size_t)(row0 + 8) * Nout + col) = make_float2(v2, v3);
                } else {
                    __half2 h01 = __floats2half2_rn(v0, v1);
                    __half2 h23 = __floats2half2_rn(v2, v3);
                    *(__half2*)(Ch + (size_t)row0 * Nout + col)       = h01;
                    *(__half2*)(Ch + (size_t)(row0 + 8) * Nout + col) = h23;
                }
            }
        }
    }
}

// -------------------- K5: pairwise cosine similarity --------------------
__global__ void __launch_bounds__(128) k_cosine(float* __restrict__ out)
{
    int b = blockIdx.x;
    const float* e1 = g_emb + (2 * b) * HE;
    const float* e2 = e1 + HE;
    int t = threadIdx.x;
    float d = 0.f, s1 = 0.f, s2 = 0.f;
    for (int j = t; j < HE; j += 128) {
        float x = e1[j], y = e2[j];
        d += x * y; s1 += x * x; s2 += y * y;
    }
    #pragma unroll
    for (int o = 16; o > 0; o >>= 1) {
        d  += __shfl_down_sync(0xffffffffu, d, o);
        s1 += __shfl_down_sync(0xffffffffu, s1, o);
        s2 += __shfl_down_sync(0xffffffffu, s2, o);
    }
    __shared__ float sd[4], sa[4], sb[4];
    int w = t >> 5;
    if ((t & 31) == 0) { sd[w] = d; sa[w] = s1; sb[w] = s2; }
    __syncthreads();
    if (t == 0) {
        d  = sd[0] + sd[1] + sd[2] + sd[3];
        s1 = sa[0] + sa[1] + sa[2] + sa[3];
        s2 = sb[0] + sb[1] + sb[2] + sb[3];
        float n1 = fmaxf(sqrtf(s1), 1e-6f);
        float n2 = fmaxf(sqrtf(s2), 1e-6f);
        out[b] = d / (n1 * n2);
    }
}

// -------------------- launch --------------------
extern "C" void kernel_launch(void* const* d_in, const int* in_sizes, int n_in,
                              void* d_out, int out_size)
{
    const float* mz       = (const float*)d_in[0];
    const float* inten    = (const float*)d_in[1];
    const float* binner_w = (const float*)d_in[2];
    const float* binner_b = (const float*)d_in[3];
    const float* w0       = (const float*)d_in[4];
    const float* b0       = (const float*)d_in[5];
    const float* w1       = (const float*)d_in[6];
    const float* b1       = (const float*)d_in[7];
    const float* w2       = (const float*)d_in[8];
    const float* b2       = (const float*)d_in[9];
    const float* we       = (const float*)d_in[10];
    const float* be       = (const float*)d_in[11];
    float* out = (float*)d_out;

    __half *xs, *w0h, *w1h, *w2h, *weh, *h0h, *h1h, *h2h;
    float* emb;
    cudaGetSymbolAddress((void**)&xs,  g_xs);
    cudaGetSymbolAddress((void**)&w0h, g_w0h);
    cudaGetSymbolAddress((void**)&w1h, g_w1h);
    cudaGetSymbolAddress((void**)&w2h, g_w2h);
    cudaGetSymbolAddress((void**)&weh, g_weh);
    cudaGetSymbolAddress((void**)&h0h, g_h0h);
    cudaGetSymbolAddress((void**)&h1h, g_h1h);
    cudaGetSymbolAddress((void**)&h2h, g_h2h);
    cudaGetSymbolAddress((void**)&emb, g_emb);

    k_build<<<NROWS, NPEAK>>>(mz, inten, binner_w);
    k_xs<<<NROWS, 128>>>(binner_b);

    // weight conversions (pads stay zero via device-global zero-init)
    {
        int n0q = (BOUT * H0) / 4;    // 2,499,750
        int n1q = (H0 * H1) / 4;      // 200,000
        int n2q = (H1 * H2) / 4;      // 160,000
        int neq = (H2 * HE) / 4;      // 80,000
        k_wconv<<<(n0q + 255) / 256, 256>>>(w0, w0h, n0q);
        k_wconv<<<(n1q + 255) / 256, 256>>>(w1, w1h, n1q);
        k_wconv<<<(n2q + 255) / 256, 256>>>(w2, w2h, n2q);
        k_wconv<<<(neq + 255) / 256, 256>>>(we, weh, neq);
    }

    // h0 = relu(xs @ w0 + b0): [512,10016] x [10016,1000]
    {
        dim3 g0((H0 + 63) / 64, NROWS / 64);
        k_hgemm<<<g0, 128>>>(xs, w0h, b0, h0h, nullptr, BOUTP, H0, H0P, 1);
        dim3 g1((H1 + 63) / 64, NROWS / 64);
        k_hgemm<<<g1, 128>>>(h0h, w1h, b1, h1h, nullptr, H0P, H1, H1, 1);
        dim3 g2((H2 + 63) / 64, NROWS / 64);
        k_hgemm<<<g2, 128>>>(h1h, w2h, b2, h2h, nullptr, H1, H2, H2, 1);
        dim3 g3((HE + 63) / 64, NROWS / 64);
        k_hgemm<<<g3, 128>>>(h2h, weh, be, nullptr, emb, H2, HE, HE, 0);
    }

    k_cosine<<<256, 128>>>(out);
    (void)in_sizes; (void)n_in; (void)out_size;
}